// round 2
// baseline (speedup 1.0000x reference)
#include <cuda_runtime.h>
#include <math.h>
#include <float.h>

#define D 128
#define BM 128
#define BN 128
#define NSUB 8
#define SPAD 132          // padded k-major smem row stride (floats), 16B-aligned rows
#define CHMAX 128
#define MAXB 4096
#define MAXP 131072
#define THREADS 256

// ---------------- device scratch (static: no allocations allowed) ----------------
__device__ float g_inv_pn[MAXP];
__device__ float g_inv_sn[MAXB];
__device__ float g_part_sum[(size_t)MAXB * CHMAX];
__device__ float g_part_val[(size_t)MAXB * CHMAX * 3];
__device__ int   g_part_idx[(size_t)MAXB * CHMAX * 3];

// degree-7 Taylor exp on [-1,1]; rel err ~1e-5, pure FFMA (avoids MUFU bottleneck)
__device__ __forceinline__ float expq(float x) {
    float r = 1.9841270e-4f;               // 1/5040
    r = fmaf(r, x, 1.3888889e-3f);         // 1/720
    r = fmaf(r, x, 8.3333333e-3f);         // 1/120
    r = fmaf(r, x, 4.1666667e-2f);         // 1/24
    r = fmaf(r, x, 1.6666667e-1f);         // 1/6
    r = fmaf(r, x, 0.5f);
    r = fmaf(r, x, 1.0f);
    r = fmaf(r, x, 1.0f);
    return r;
}

// online top-3 insert with (value desc, index asc) tie-break — matches jax.lax.top_k
__device__ __forceinline__ void ins_tie(float c, int ci,
    float& v0, int& i0, float& v1, int& i1, float& v2, int& i2) {
    if ((c > v2) || (c == v2 && ci < i2)) {
        if ((c > v1) || (c == v1 && ci < i1)) {
            if ((c > v0) || (c == v0 && ci < i0)) {
                v2 = v1; i2 = i1; v1 = v0; i1 = i0; v0 = c; i0 = ci;
            } else { v2 = v1; i2 = i1; v1 = c; i1 = ci; }
        } else     { v2 = c;  i2 = ci; }
    }
}

// ---------------- kernel 1: inverse norms  1/sqrt(sum(x^2) + D*EPS) ----------------
__global__ void norm_kernel(const float* __restrict__ x, int n, float* __restrict__ dst) {
    int row = blockIdx.x * (blockDim.x >> 5) + (threadIdx.x >> 5);
    if (row >= n) return;
    int lane = threadIdx.x & 31;
    float4 v = ((const float4*)(x + (size_t)row * D))[lane];
    float s = v.x * v.x + v.y * v.y + v.z * v.z + v.w * v.w;
    #pragma unroll
    for (int m = 16; m; m >>= 1) s += __shfl_xor_sync(0xffffffffu, s, m);
    if (lane == 0) dst[row] = 1.0f / sqrtf(s + (float)D * 1e-6f);   // IEEE sqrt+div
}

// ---------------- kernel 2: fused cos-GEMM + streaming (Z, top-3) ----------------
__global__ void __launch_bounds__(THREADS, 1)
main_kernel(const float* __restrict__ sess, const float* __restrict__ pool, int B, int P) {
    extern __shared__ float sm[];
    float* As = sm;                       // [D][SPAD] k-major sess tile
    float* Bs = sm + (size_t)D * SPAD;    // [D][SPAD] k-major pool tile
    __shared__ float s_invs[BM];
    __shared__ float s_invp[BN];

    const int tid = threadIdx.x;
    const int tx = tid & 15;              // col group  (8 cols each)
    const int ty = tid >> 4;              // row group  (8 rows each)
    const int rowbase = blockIdx.y * BM;
    const int cbase = blockIdx.x * (BN * NSUB);

    const int lane = tid & 31;            // loader mapping: lane -> row (conflict-free STS)
    const int wk = tid >> 5;              // 0..7 -> k4 chunk

    // load sess tile once (transposed to k-major)
    #pragma unroll
    for (int ri = 0; ri < 4; ri++) {
        int m = ri * 32 + lane;
        int gr = rowbase + m;
        #pragma unroll
        for (int ki = 0; ki < 4; ki++) {
            int k4 = ki * 8 + wk;
            float4 v = make_float4(0.f, 0.f, 0.f, 0.f);
            if (gr < B) v = *(const float4*)(sess + (size_t)gr * D + k4 * 4);
            As[(k4 * 4 + 0) * SPAD + m] = v.x;
            As[(k4 * 4 + 1) * SPAD + m] = v.y;
            As[(k4 * 4 + 2) * SPAD + m] = v.z;
            As[(k4 * 4 + 3) * SPAD + m] = v.w;
        }
    }
    if (tid < BM) s_invs[tid] = (rowbase + tid < B) ? g_inv_sn[rowbase + tid] : 0.f;
    __syncthreads();

    float invs_r[8];
    #pragma unroll
    for (int i = 0; i < 8; i++) invs_r[i] = s_invs[ty * 8 + i];

    // per-thread running state: 8 rows
    float zsum[8];
    float tv0[8], tv1[8], tv2[8];
    int   ti0[8], ti1[8], ti2[8];
    #pragma unroll
    for (int i = 0; i < 8; i++) {
        zsum[i] = 0.f;
        tv0[i] = tv1[i] = tv2[i] = -FLT_MAX;
        ti0[i] = ti1[i] = ti2[i] = 0x7fffffff;
    }

    for (int s = 0; s < NSUB; s++) {
        const int pbase = cbase + s * BN;
        __syncthreads();                  // protect Bs from previous readers
        #pragma unroll
        for (int ri = 0; ri < 4; ri++) {
            int n = ri * 32 + lane;
            int gp = pbase + n;
            #pragma unroll
            for (int ki = 0; ki < 4; ki++) {
                int k4 = ki * 8 + wk;
                float4 v = make_float4(0.f, 0.f, 0.f, 0.f);
                if (gp < P) v = *(const float4*)(pool + (size_t)gp * D + k4 * 4);
                Bs[(k4 * 4 + 0) * SPAD + n] = v.x;
                Bs[(k4 * 4 + 1) * SPAD + n] = v.y;
                Bs[(k4 * 4 + 2) * SPAD + n] = v.z;
                Bs[(k4 * 4 + 3) * SPAD + n] = v.w;
            }
        }
        if (tid < BN) s_invp[tid] = (pbase + tid < P) ? g_inv_pn[pbase + tid] : 0.f;
        __syncthreads();

        float acc[8][8];
        #pragma unroll
        for (int i = 0; i < 8; i++)
            #pragma unroll
            for (int j = 0; j < 8; j++) acc[i][j] = 0.f;

        #pragma unroll 8
        for (int k = 0; k < D; k++) {
            float4 a0 = *(const float4*)(As + k * SPAD + ty * 8);
            float4 a1 = *(const float4*)(As + k * SPAD + ty * 8 + 4);
            float4 b0 = *(const float4*)(Bs + k * SPAD + tx * 8);
            float4 b1 = *(const float4*)(Bs + k * SPAD + tx * 8 + 4);
            float a[8] = {a0.x, a0.y, a0.z, a0.w, a1.x, a1.y, a1.z, a1.w};
            float b[8] = {b0.x, b0.y, b0.z, b0.w, b1.x, b1.y, b1.z, b1.w};
            #pragma unroll
            for (int i = 0; i < 8; i++)
                #pragma unroll
                for (int j = 0; j < 8; j++)
                    acc[i][j] = fmaf(a[i], b[j], acc[i][j]);
        }

        // fused epilogue: cos, poly-exp accumulate, top-3 track
        float invp_r[8];
        #pragma unroll
        for (int j = 0; j < 8; j++) invp_r[j] = s_invp[tx * 8 + j];
        const int colbase = pbase + tx * 8;
        const int nvalid = P - colbase;   // j < nvalid are in-range
        #pragma unroll
        for (int i = 0; i < 8; i++) {
            float zr = 0.f;
            #pragma unroll
            for (int j = 0; j < 8; j++) {
                if (j < nvalid) {
                    float c = acc[i][j] * invs_r[i] * invp_r[j];
                    zr += expq(c);
                    if (c > tv2[i]) {     // stream is index-increasing: strict > keeps ties right
                        int col = colbase + j;
                        if (c > tv1[i]) {
                            if (c > tv0[i]) {
                                tv2[i] = tv1[i]; ti2[i] = ti1[i];
                                tv1[i] = tv0[i]; ti1[i] = ti0[i];
                                tv0[i] = c;      ti0[i] = col;
                            } else { tv2[i] = tv1[i]; ti2[i] = ti1[i]; tv1[i] = c; ti1[i] = col; }
                        } else     { tv2[i] = c; ti2[i] = col; }
                    }
                }
            }
            zsum[i] += zr;
        }
    }

    // butterfly merge across the 16 tx lanes that share each row, then write partials
    #pragma unroll
    for (int i = 0; i < 8; i++) {
        float z = zsum[i];
        float v0 = tv0[i], v1 = tv1[i], v2 = tv2[i];
        int   i0 = ti0[i], i1 = ti1[i], i2 = ti2[i];
        #pragma unroll
        for (int m = 8; m; m >>= 1) {
            z += __shfl_xor_sync(0xffffffffu, z, m);
            float ov0 = __shfl_xor_sync(0xffffffffu, v0, m);
            int   oi0 = __shfl_xor_sync(0xffffffffu, i0, m);
            float ov1 = __shfl_xor_sync(0xffffffffu, v1, m);
            int   oi1 = __shfl_xor_sync(0xffffffffu, i1, m);
            float ov2 = __shfl_xor_sync(0xffffffffu, v2, m);
            int   oi2 = __shfl_xor_sync(0xffffffffu, i2, m);
            ins_tie(ov0, oi0, v0, i0, v1, i1, v2, i2);
            ins_tie(ov1, oi1, v0, i0, v1, i1, v2, i2);
            ins_tie(ov2, oi2, v0, i0, v1, i1, v2, i2);
        }
        if (tx == 0) {
            int row = rowbase + ty * 8 + i;
            if (row < B) {
                size_t base = (size_t)row * CHMAX + blockIdx.x;
                g_part_sum[base] = z;
                g_part_val[base * 3 + 0] = v0; g_part_idx[base * 3 + 0] = i0;
                g_part_val[base * 3 + 1] = v1; g_part_idx[base * 3 + 1] = i1;
                g_part_val[base * 3 + 2] = v2; g_part_idx[base * 3 + 2] = i2;
            }
        }
    }
}

// ---------------- kernel 3: per-row merge + softmaxes + gather + write outputs ----------------
__global__ void reduce_kernel(const float* __restrict__ pool, float* __restrict__ out,
                              int B, int P, int nchunk) {
    int warp = (blockIdx.x * blockDim.x + threadIdx.x) >> 5;
    int lane = threadIdx.x & 31;
    if (warp >= B) return;
    const int row = warp;

    float Z = 0.f;
    float v0 = -FLT_MAX, v1 = -FLT_MAX, v2 = -FLT_MAX;
    int   i0 = 0x7fffffff, i1 = 0x7fffffff, i2 = 0x7fffffff;
    for (int c = lane; c < nchunk; c += 32) {
        size_t base = (size_t)row * CHMAX + c;
        Z += g_part_sum[base];
        ins_tie(g_part_val[base * 3 + 0], g_part_idx[base * 3 + 0], v0, i0, v1, i1, v2, i2);
        ins_tie(g_part_val[base * 3 + 1], g_part_idx[base * 3 + 1], v0, i0, v1, i1, v2, i2);
        ins_tie(g_part_val[base * 3 + 2], g_part_idx[base * 3 + 2], v0, i0, v1, i1, v2, i2);
    }
    #pragma unroll
    for (int m = 16; m; m >>= 1) {
        Z += __shfl_xor_sync(0xffffffffu, Z, m);
        float ov0 = __shfl_xor_sync(0xffffffffu, v0, m);
        int   oi0 = __shfl_xor_sync(0xffffffffu, i0, m);
        float ov1 = __shfl_xor_sync(0xffffffffu, v1, m);
        int   oi1 = __shfl_xor_sync(0xffffffffu, i1, m);
        float ov2 = __shfl_xor_sync(0xffffffffu, v2, m);
        int   oi2 = __shfl_xor_sync(0xffffffffu, i2, m);
        ins_tie(ov0, oi0, v0, i0, v1, i1, v2, i2);
        ins_tie(ov1, oi1, v0, i0, v1, i1, v2, i2);
        ins_tie(ov2, oi2, v0, i0, v1, i1, v2, i2);
    }

    // first softmax probs of the 3 winners; second (3-way) softmax -> weights
    float iz = 1.0f / Z;
    float p0 = expq(v0) * iz, p1 = expq(v1) * iz, p2 = expq(v2) * iz;
    float mx = fmaxf(p0, fmaxf(p1, p2));
    float e0 = expf(p0 - mx), e1 = expf(p1 - mx), e2 = expf(p2 - mx);
    float si = 1.0f / (e0 + e1 + e2);
    float w0 = e0 * si, w1 = e1 * si, w2 = e2 * si;

    const size_t cos_off = (size_t)B * D;
    if (lane == 0) {
        out[cos_off + (size_t)row * 3 + 0] = w0;
        out[cos_off + (size_t)row * 3 + 1] = w1;
        out[cos_off + (size_t)row * 3 + 2] = w2;
    }

    float4 q0 = ((const float4*)(pool + (size_t)i0 * D))[lane];
    float4 q1 = ((const float4*)(pool + (size_t)i1 * D))[lane];
    float4 q2 = ((const float4*)(pool + (size_t)i2 * D))[lane];
    float4 nb;
    nb.x = fmaf(w0, q0.x, fmaf(w1, q1.x, w2 * q2.x));
    nb.y = fmaf(w0, q0.y, fmaf(w1, q1.y, w2 * q2.y));
    nb.z = fmaf(w0, q0.z, fmaf(w1, q1.z, w2 * q2.z));
    nb.w = fmaf(w0, q0.w, fmaf(w1, q1.w, w2 * q2.w));
    ((float4*)(out + (size_t)row * D))[lane] = nb;

    const size_t sbase = cos_off + (size_t)B * 3;
    ((float4*)(out + sbase + ((size_t)row * 3 + 0) * D))[lane] = q0;
    ((float4*)(out + sbase + ((size_t)row * 3 + 1) * D))[lane] = q1;
    ((float4*)(out + sbase + ((size_t)row * 3 + 2) * D))[lane] = q2;
}

// ---------------- launch ----------------
extern "C" void kernel_launch(void* const* d_in, const int* in_sizes, int n_in,
                              void* d_out, int out_size) {
    const float* sess = (const float*)d_in[0];
    const float* pool = (const float*)d_in[1];
    float* out = (float*)d_out;
    const int B = in_sizes[0] / D;
    const int P = in_sizes[1] / D;

    float *inv_pn, *inv_sn;
    cudaGetSymbolAddress((void**)&inv_pn, g_inv_pn);
    cudaGetSymbolAddress((void**)&inv_sn, g_inv_sn);

    norm_kernel<<<(P + 7) / 8, 256>>>(pool, P, inv_pn);
    norm_kernel<<<(B + 7) / 8, 256>>>(sess, B, inv_sn);

    const int nchunk = (P + BN * NSUB - 1) / (BN * NSUB);   // 98 for P=100000
    const size_t smem = 2 * (size_t)D * SPAD * sizeof(float); // 132 KB
    cudaFuncSetAttribute(main_kernel, cudaFuncAttributeMaxDynamicSharedMemorySize, (int)smem);
    dim3 grid(nchunk, (B + BM - 1) / BM);
    main_kernel<<<grid, THREADS, smem>>>(sess, pool, B, P);

    reduce_kernel<<<(B * 32 + 255) / 256, 256>>>(pool, out, B, P, nchunk);
}

// round 3
// speedup vs baseline: 1.1115x; 1.1115x over previous
#include <cuda_runtime.h>
#include <math.h>
#include <float.h>

#define D 128
#define BM 128
#define BN 256
#define NSUB 4
#define SPAD 132          // As row stride (floats)
#define SPAD2 260         // Bs row stride (floats)
#define CHMAX 128
#define MAXB 4096
#define MAXP 131072
#define THREADS 256

typedef unsigned long long u64;

// ---------------- device scratch (static: no allocations allowed) ----------------
__device__ float g_inv_pn[MAXP];
__device__ float g_inv_sn[MAXB];
__device__ float g_part_sum[(size_t)MAXB * CHMAX];
__device__ float g_part_val[(size_t)MAXB * CHMAX * 3];
__device__ int   g_part_idx[(size_t)MAXB * CHMAX * 3];

// ---------------- packed f32x2 helpers (SASS FFMA2 path, ptxas won't emit from C++) ----------
__device__ __forceinline__ u64 pk2(float lo, float hi) {
    u64 r; asm("mov.b64 %0, {%1, %2};" : "=l"(r)
               : "r"(__float_as_uint(lo)), "r"(__float_as_uint(hi)));
    return r;
}
__device__ __forceinline__ u64 bc2(float x) {
    u64 r; asm("mov.b64 %0, {%1, %1};" : "=l"(r) : "r"(__float_as_uint(x)));
    return r;
}
__device__ __forceinline__ void upk2(u64 v, float& lo, float& hi) {
    unsigned a, b; asm("mov.b64 {%0, %1}, %2;" : "=r"(a), "=r"(b) : "l"(v));
    lo = __uint_as_float(a); hi = __uint_as_float(b);
}
__device__ __forceinline__ u64 fma2(u64 a, u64 b, u64 c) {
    u64 d; asm("fma.rn.f32x2 %0, %1, %2, %3;" : "=l"(d) : "l"(a), "l"(b), "l"(c));
    return d;
}
__device__ __forceinline__ u64 mul2(u64 a, u64 b) {
    u64 d; asm("mul.rn.f32x2 %0, %1, %2;" : "=l"(d) : "l"(a), "l"(b));
    return d;
}
__device__ __forceinline__ u64 add2(u64 a, u64 b) {
    u64 d; asm("add.rn.f32x2 %0, %1, %2;" : "=l"(d) : "l"(a), "l"(b));
    return d;
}

// degree-7 Taylor exp on [-1,1]; rel err ~1e-5, pure FFMA (avoids MUFU bottleneck)
__device__ __forceinline__ float expq(float x) {
    float r = 1.9841270e-4f;
    r = fmaf(r, x, 1.3888889e-3f);
    r = fmaf(r, x, 8.3333333e-3f);
    r = fmaf(r, x, 4.1666667e-2f);
    r = fmaf(r, x, 1.6666667e-1f);
    r = fmaf(r, x, 0.5f);
    r = fmaf(r, x, 1.0f);
    r = fmaf(r, x, 1.0f);
    return r;
}
__device__ __forceinline__ u64 expq2(u64 x, const u64* C) {
    u64 r = C[0];
    #pragma unroll
    for (int t = 1; t < 8; t++) r = fma2(r, x, C[t]);
    return r;
}

// online top-3 insert with (value desc, index asc) tie-break — matches jax.lax.top_k
__device__ __forceinline__ void ins_tie(float c, int ci,
    float& v0, int& i0, float& v1, int& i1, float& v2, int& i2) {
    if ((c > v2) || (c == v2 && ci < i2)) {
        if ((c > v1) || (c == v1 && ci < i1)) {
            if ((c > v0) || (c == v0 && ci < i0)) {
                v2 = v1; i2 = i1; v1 = v0; i1 = i0; v0 = c; i0 = ci;
            } else { v2 = v1; i2 = i1; v1 = c; i1 = ci; }
        } else     { v2 = c;  i2 = ci; }
    }
}
// streaming insert (index strictly increasing): strict > preserves tie-break
__device__ __forceinline__ void ins_stream(float c, int col,
    float& v0, int& i0, float& v1, int& i1, float& v2, int& i2) {
    if (c > v2) {
        if (c > v1) {
            if (c > v0) { v2 = v1; i2 = i1; v1 = v0; i1 = i0; v0 = c; i0 = col; }
            else        { v2 = v1; i2 = i1; v1 = c;  i1 = col; }
        } else          { v2 = c;  i2 = col; }
    }
}

// ---------------- kernel 1: inverse norms  1/sqrt(sum(x^2) + D*EPS) ----------------
__global__ void norm_kernel(const float* __restrict__ x, int n, float* __restrict__ dst) {
    int row = blockIdx.x * (blockDim.x >> 5) + (threadIdx.x >> 5);
    if (row >= n) return;
    int lane = threadIdx.x & 31;
    float4 v = ((const float4*)(x + (size_t)row * D))[lane];
    float s = v.x * v.x + v.y * v.y + v.z * v.z + v.w * v.w;
    #pragma unroll
    for (int m = 16; m; m >>= 1) s += __shfl_xor_sync(0xffffffffu, s, m);
    if (lane == 0) dst[row] = 1.0f / sqrtf(s + (float)D * 1e-6f);
}

// ---------------- kernel 2: fused cos-GEMM (FFMA2) + streaming (Z, top-3) ----------------
__global__ void __launch_bounds__(THREADS, 1)
main_kernel(const float* __restrict__ sess, const float* __restrict__ pool, int B, int P) {
    extern __shared__ float sm[];
    float* As = sm;                       // [D][SPAD]  k-major sess tile
    float* Bs = sm + (size_t)D * SPAD;    // [D][SPAD2] k-major pool tile
    __shared__ float s_invs[BM];
    __shared__ float s_invp[BN];

    const int tid = threadIdx.x;
    const int tx = tid & 15;              // col group
    const int ty = tid >> 4;              // row group
    const int rowbase = blockIdx.y * BM;
    const int cbase = blockIdx.x * (BN * NSUB);

    const int lane = tid & 31;            // loader: lane -> row (conflict-free STS)
    const int wk = tid >> 5;              // 0..7 -> k4 chunk

    // load sess tile once (transposed to k-major)
    #pragma unroll
    for (int ri = 0; ri < 4; ri++) {
        int m = ri * 32 + lane;
        int gr = rowbase + m;
        #pragma unroll
        for (int ki = 0; ki < 4; ki++) {
            int k4 = ki * 8 + wk;
            float4 v = make_float4(0.f, 0.f, 0.f, 0.f);
            if (gr < B) v = *(const float4*)(sess + (size_t)gr * D + k4 * 4);
            As[(k4 * 4 + 0) * SPAD + m] = v.x;
            As[(k4 * 4 + 1) * SPAD + m] = v.y;
            As[(k4 * 4 + 2) * SPAD + m] = v.z;
            As[(k4 * 4 + 3) * SPAD + m] = v.w;
        }
    }
    if (tid < BM) s_invs[tid] = (rowbase + tid < B) ? g_inv_sn[rowbase + tid] : 0.f;
    __syncthreads();

    // per-thread rows: q = ip*2 + lane2, row offset within tile:
    //   h = ip>>1, p = ip&1 -> rowoff = h*64 + ty*4 + p*2 + lane2
    int rowoff[8];
    #pragma unroll
    for (int q = 0; q < 8; q++) {
        int ip = q >> 1, l2 = q & 1;
        rowoff[q] = (ip >> 1) * 64 + ty * 4 + (ip & 1) * 2 + l2;
    }
    u64 invs2[4];
    #pragma unroll
    for (int ip = 0; ip < 4; ip++)
        invs2[ip] = pk2(s_invs[rowoff[ip * 2]], s_invs[rowoff[ip * 2 + 1]]);

    // exp poly coefficients, packed (highest first)
    u64 EC[8];
    EC[0] = bc2(1.9841270e-4f); EC[1] = bc2(1.3888889e-3f);
    EC[2] = bc2(8.3333333e-3f); EC[3] = bc2(4.1666667e-2f);
    EC[4] = bc2(1.6666667e-1f); EC[5] = bc2(0.5f);
    EC[6] = bc2(1.0f);          EC[7] = bc2(1.0f);

    // per-thread running state: 8 rows
    u64   z2[4];
    float tv0[8], tv1[8], tv2[8];
    int   ti0[8], ti1[8], ti2[8];
    #pragma unroll
    for (int ip = 0; ip < 4; ip++) z2[ip] = 0ull;
    #pragma unroll
    for (int q = 0; q < 8; q++) {
        tv0[q] = tv1[q] = tv2[q] = -FLT_MAX;
        ti0[q] = ti1[q] = ti2[q] = 0x7fffffff;
    }

    for (int s = 0; s < NSUB; s++) {
        const int pbase = cbase + s * BN;
        __syncthreads();                  // protect Bs from previous readers
        #pragma unroll
        for (int ri = 0; ri < 8; ri++) {
            int n = ri * 32 + lane;
            int gp = pbase + n;
            #pragma unroll
            for (int ki = 0; ki < 4; ki++) {
                int k4 = ki * 8 + wk;
                float4 v = make_float4(0.f, 0.f, 0.f, 0.f);
                if (gp < P) v = *(const float4*)(pool + (size_t)gp * D + k4 * 4);
                Bs[(k4 * 4 + 0) * SPAD2 + n] = v.x;
                Bs[(k4 * 4 + 1) * SPAD2 + n] = v.y;
                Bs[(k4 * 4 + 2) * SPAD2 + n] = v.z;
                Bs[(k4 * 4 + 3) * SPAD2 + n] = v.w;
            }
        }
        s_invp[tid] = (pbase + tid < P) ? g_inv_pn[pbase + tid] : 0.f;
        __syncthreads();

        u64 acc2[4][16];
        #pragma unroll
        for (int ip = 0; ip < 4; ip++)
            #pragma unroll
            for (int j = 0; j < 16; j++) acc2[ip][j] = 0ull;

        #pragma unroll 4
        for (int k = 0; k < D; k++) {
            const float* ar = As + k * SPAD + ty * 4;
            ulonglong2 aA = *(const ulonglong2*)(ar);        // rows ty*4+0..3   (h=0)
            ulonglong2 aB = *(const ulonglong2*)(ar + 64);   // rows 64+ty*4+0..3 (h=1)
            u64 av[4] = {aA.x, aA.y, aB.x, aB.y};
            const float* br = Bs + k * SPAD2 + tx * 4;
            #pragma unroll
            for (int g = 0; g < 4; g++) {
                float4 bf = *(const float4*)(br + g * 64);
                u64 b0 = bc2(bf.x), b1 = bc2(bf.y), b2 = bc2(bf.z), b3 = bc2(bf.w);
                #pragma unroll
                for (int ip = 0; ip < 4; ip++) {
                    acc2[ip][g * 4 + 0] = fma2(av[ip], b0, acc2[ip][g * 4 + 0]);
                    acc2[ip][g * 4 + 1] = fma2(av[ip], b1, acc2[ip][g * 4 + 1]);
                    acc2[ip][g * 4 + 2] = fma2(av[ip], b2, acc2[ip][g * 4 + 2]);
                    acc2[ip][g * 4 + 3] = fma2(av[ip], b3, acc2[ip][g * 4 + 3]);
                }
            }
        }

        // fused epilogue: cos, poly-exp accumulate (f32x2), top-3 track (scalar)
        #pragma unroll
        for (int j = 0; j < 16; j++) {
            int nloc = (j >> 2) * 64 + tx * 4 + (j & 3);
            int col = pbase + nloc;
            if (col >= P) continue;
            u64 ip2 = bc2(s_invp[nloc]);
            #pragma unroll
            for (int ipp = 0; ipp < 4; ipp++) {
                u64 c2 = mul2(mul2(acc2[ipp][j], invs2[ipp]), ip2);
                z2[ipp] = add2(z2[ipp], expq2(c2, EC));
                float c0, c1; upk2(c2, c0, c1);
                int q0 = ipp * 2, q1 = ipp * 2 + 1;
                ins_stream(c0, col, tv0[q0], ti0[q0], tv1[q0], ti1[q0], tv2[q0], ti2[q0]);
                ins_stream(c1, col, tv0[q1], ti0[q1], tv1[q1], ti1[q1], tv2[q1], ti2[q1]);
            }
        }
    }

    // butterfly merge across the 16 tx lanes sharing each row, then write partials
    #pragma unroll
    for (int q = 0; q < 8; q++) {
        float zlo, zhi; upk2(z2[q >> 1], zlo, zhi);
        float z = (q & 1) ? zhi : zlo;
        float v0 = tv0[q], v1 = tv1[q], v2 = tv2[q];
        int   i0 = ti0[q], i1 = ti1[q], i2 = ti2[q];
        #pragma unroll
        for (int m = 8; m; m >>= 1) {
            z += __shfl_xor_sync(0xffffffffu, z, m);
            float ov0 = __shfl_xor_sync(0xffffffffu, v0, m);
            int   oi0 = __shfl_xor_sync(0xffffffffu, i0, m);
            float ov1 = __shfl_xor_sync(0xffffffffu, v1, m);
            int   oi1 = __shfl_xor_sync(0xffffffffu, i1, m);
            float ov2 = __shfl_xor_sync(0xffffffffu, v2, m);
            int   oi2 = __shfl_xor_sync(0xffffffffu, i2, m);
            ins_tie(ov0, oi0, v0, i0, v1, i1, v2, i2);
            ins_tie(ov1, oi1, v0, i0, v1, i1, v2, i2);
            ins_tie(ov2, oi2, v0, i0, v1, i1, v2, i2);
        }
        if (tx == 0) {
            int row = rowbase + rowoff[q];
            if (row < B) {
                size_t base = (size_t)row * CHMAX + blockIdx.x;
                g_part_sum[base] = z;
                g_part_val[base * 3 + 0] = v0; g_part_idx[base * 3 + 0] = i0;
                g_part_val[base * 3 + 1] = v1; g_part_idx[base * 3 + 1] = i1;
                g_part_val[base * 3 + 2] = v2; g_part_idx[base * 3 + 2] = i2;
            }
        }
    }
}

// ---------------- kernel 3: per-row merge + softmaxes + gather + write outputs ----------------
__global__ void reduce_kernel(const float* __restrict__ pool, float* __restrict__ out,
                              int B, int P, int nchunk) {
    int warp = (blockIdx.x * blockDim.x + threadIdx.x) >> 5;
    int lane = threadIdx.x & 31;
    if (warp >= B) return;
    const int row = warp;

    float Z = 0.f;
    float v0 = -FLT_MAX, v1 = -FLT_MAX, v2 = -FLT_MAX;
    int   i0 = 0x7fffffff, i1 = 0x7fffffff, i2 = 0x7fffffff;
    for (int c = lane; c < nchunk; c += 32) {
        size_t base = (size_t)row * CHMAX + c;
        Z += g_part_sum[base];
        ins_tie(g_part_val[base * 3 + 0], g_part_idx[base * 3 + 0], v0, i0, v1, i1, v2, i2);
        ins_tie(g_part_val[base * 3 + 1], g_part_idx[base * 3 + 1], v0, i0, v1, i1, v2, i2);
        ins_tie(g_part_val[base * 3 + 2], g_part_idx[base * 3 + 2], v0, i0, v1, i1, v2, i2);
    }
    #pragma unroll
    for (int m = 16; m; m >>= 1) {
        Z += __shfl_xor_sync(0xffffffffu, Z, m);
        float ov0 = __shfl_xor_sync(0xffffffffu, v0, m);
        int   oi0 = __shfl_xor_sync(0xffffffffu, i0, m);
        float ov1 = __shfl_xor_sync(0xffffffffu, v1, m);
        int   oi1 = __shfl_xor_sync(0xffffffffu, i1, m);
        float ov2 = __shfl_xor_sync(0xffffffffu, v2, m);
        int   oi2 = __shfl_xor_sync(0xffffffffu, i2, m);
        ins_tie(ov0, oi0, v0, i0, v1, i1, v2, i2);
        ins_tie(ov1, oi1, v0, i0, v1, i1, v2, i2);
        ins_tie(ov2, oi2, v0, i0, v1, i1, v2, i2);
    }

    float iz = 1.0f / Z;
    float p0 = expq(v0) * iz, p1 = expq(v1) * iz, p2 = expq(v2) * iz;
    float mx = fmaxf(p0, fmaxf(p1, p2));
    float e0 = expf(p0 - mx), e1 = expf(p1 - mx), e2 = expf(p2 - mx);
    float si = 1.0f / (e0 + e1 + e2);
    float w0 = e0 * si, w1 = e1 * si, w2 = e2 * si;

    const size_t cos_off = (size_t)B * D;
    if (lane == 0) {
        out[cos_off + (size_t)row * 3 + 0] = w0;
        out[cos_off + (size_t)row * 3 + 1] = w1;
        out[cos_off + (size_t)row * 3 + 2] = w2;
    }

    float4 q0 = ((const float4*)(pool + (size_t)i0 * D))[lane];
    float4 q1 = ((const float4*)(pool + (size_t)i1 * D))[lane];
    float4 q2 = ((const float4*)(pool + (size_t)i2 * D))[lane];
    float4 nb;
    nb.x = fmaf(w0, q0.x, fmaf(w1, q1.x, w2 * q2.x));
    nb.y = fmaf(w0, q0.y, fmaf(w1, q1.y, w2 * q2.y));
    nb.z = fmaf(w0, q0.z, fmaf(w1, q1.z, w2 * q2.z));
    nb.w = fmaf(w0, q0.w, fmaf(w1, q1.w, w2 * q2.w));
    ((float4*)(out + (size_t)row * D))[lane] = nb;

    const size_t sbase = cos_off + (size_t)B * 3;
    ((float4*)(out + sbase + ((size_t)row * 3 + 0) * D))[lane] = q0;
    ((float4*)(out + sbase + ((size_t)row * 3 + 1) * D))[lane] = q1;
    ((float4*)(out + sbase + ((size_t)row * 3 + 2) * D))[lane] = q2;
}

// ---------------- launch ----------------
extern "C" void kernel_launch(void* const* d_in, const int* in_sizes, int n_in,
                              void* d_out, int out_size) {
    const float* sess = (const float*)d_in[0];
    const float* pool = (const float*)d_in[1];
    float* out = (float*)d_out;
    const int B = in_sizes[0] / D;
    const int P = in_sizes[1] / D;

    float *inv_pn, *inv_sn;
    cudaGetSymbolAddress((void**)&inv_pn, g_inv_pn);
    cudaGetSymbolAddress((void**)&inv_sn, g_inv_sn);

    norm_kernel<<<(P + 7) / 8, 256>>>(pool, P, inv_pn);
    norm_kernel<<<(B + 7) / 8, 256>>>(sess, B, inv_sn);

    const int nchunk = (P + BN * NSUB - 1) / (BN * NSUB);        // 98 for P=100000
    const size_t smem = ((size_t)D * SPAD + (size_t)D * SPAD2) * sizeof(float); // ~196KB
    cudaFuncSetAttribute(main_kernel, cudaFuncAttributeMaxDynamicSharedMemorySize, (int)smem);
    dim3 grid(nchunk, (B + BM - 1) / BM);
    main_kernel<<<grid, THREADS, smem>>>(sess, pool, B, P);

    reduce_kernel<<<(B * 32 + 255) / 256, 256>>>(pool, out, B, P, nchunk);
}

// round 5
// speedup vs baseline: 1.3015x; 1.1709x over previous
#include <cuda_runtime.h>
#include <cuda_bf16.h>
#include <math.h>
#include <float.h>
#include <stdint.h>

#define D 128
#define BM 128
#define BN 256
#define KC 64
#define KEXT 384            // stored K: 3 bf16 limbs x 128
#define KSTEPS 12           // effective K = 768 over KC=64
#define NT 512
#define CHMAX 400
#define MAXB 4096
#define PROWS 100352
#define BUFSZ 49152         // A 16KB + B 32KB per stage

// ---------------- device scratch ----------------
__device__ __nv_bfloat16 g_aext[(size_t)MAXB * KEXT];
__device__ __nv_bfloat16 g_bext[(size_t)PROWS * KEXT];
__device__ float g_inv_pn[PROWS];
__device__ float g_inv_sn[MAXB];
__device__ float g_part_sum[(size_t)MAXB * CHMAX];
__device__ float g_part_val[(size_t)MAXB * CHMAX * 3];
__device__ int   g_part_idx[(size_t)MAXB * CHMAX * 3];

// ---------------- helpers ----------------
__device__ __forceinline__ uint32_t smem_u32(const void* p) {
    uint32_t a;
    asm("{ .reg .u64 t; cvta.to.shared.u64 t, %1; cvt.u32.u64 %0, t; }" : "=r"(a) : "l"(p));
    return a;
}
#define LDSM_X4(r0, r1, r2, r3, addr) \
    asm volatile("ldmatrix.sync.aligned.m8n8.x4.shared.b16 {%0,%1,%2,%3}, [%4];" \
                 : "=r"(r0), "=r"(r1), "=r"(r2), "=r"(r3) : "r"(addr))
#define MMA_BF16(d, a, b) \
    asm volatile("mma.sync.aligned.m16n8k16.row.col.f32.bf16.bf16.f32 " \
                 "{%0,%1,%2,%3}, {%4,%5,%6,%7}, {%8,%9}, {%0,%1,%2,%3};" \
                 : "+f"((d)[0]), "+f"((d)[1]), "+f"((d)[2]), "+f"((d)[3]) \
                 : "r"((a)[0]), "r"((a)[1]), "r"((a)[2]), "r"((a)[3]), \
                   "r"((b)[0]), "r"((b)[1]))
#define CP_ASYNC16(sa, ga) \
    asm volatile("cp.async.cg.shared.global [%0], [%1], 16;" :: "r"(sa), "l"(ga))
#define CP_COMMIT() asm volatile("cp.async.commit_group;" ::: "memory")

__device__ __forceinline__ float expq5(float x) {     // Z-sum exp (deg-5; ample for Z)
    float r = 8.3333333e-3f;
    r = fmaf(r, x, 4.1666667e-2f);
    r = fmaf(r, x, 1.6666667e-1f);
    r = fmaf(r, x, 0.5f);
    r = fmaf(r, x, 1.0f);
    r = fmaf(r, x, 1.0f);
    return r;
}
__device__ __forceinline__ float expq7(float x) {     // high-acc exp for winners
    float r = 1.9841270e-4f;
    r = fmaf(r, x, 1.3888889e-3f);
    r = fmaf(r, x, 8.3333333e-3f);
    r = fmaf(r, x, 4.1666667e-2f);
    r = fmaf(r, x, 1.6666667e-1f);
    r = fmaf(r, x, 0.5f);
    r = fmaf(r, x, 1.0f);
    r = fmaf(r, x, 1.0f);
    return r;
}
__device__ __forceinline__ void ins_tie(float c, int ci,
    float& v0, int& i0, float& v1, int& i1, float& v2, int& i2) {
    if ((c > v2) || (c == v2 && ci < i2)) {
        if ((c > v1) || (c == v1 && ci < i1)) {
            if ((c > v0) || (c == v0 && ci < i0)) {
                v2 = v1; i2 = i1; v1 = v0; i1 = i0; v0 = c; i0 = ci;
            } else { v2 = v1; i2 = i1; v1 = c; i1 = ci; }
        } else     { v2 = c;  i2 = ci; }
    }
}
__device__ __forceinline__ void ins_stream(float c, int col,
    float& v0, int& i0, float& v1, int& i1, float& v2, int& i2) {
    if (c > v2) {
        if (c > v1) {
            if (c > v0) { v2 = v1; i2 = i1; v1 = v0; i1 = i0; v0 = c; i0 = col; }
            else        { v2 = v1; i2 = i1; v1 = c;  i1 = col; }
        } else          { v2 = c;  i2 = col; }
    }
}

// ---------------- kernel 1: inverse norms ----------------
__global__ void norm_kernel(const float* __restrict__ x, int n, float* __restrict__ dst) {
    int row = blockIdx.x * (blockDim.x >> 5) + (threadIdx.x >> 5);
    if (row >= n) return;
    int lane = threadIdx.x & 31;
    float4 v = ((const float4*)(x + (size_t)row * D))[lane];
    float s = v.x * v.x + v.y * v.y + v.z * v.z + v.w * v.w;
    #pragma unroll
    for (int m = 16; m; m >>= 1) s += __shfl_xor_sync(0xffffffffu, s, m);
    if (lane == 0) dst[row] = 1.0f / sqrtf(s + (float)D * 1e-6f);
}

// ---------------- kernel 2: scale + 3-limb bf16 split into [row][384] ----------------
__global__ void split_kernel(const float* __restrict__ src, const float* __restrict__ inv,
                             int nvalid, long total, __nv_bfloat16* __restrict__ dst) {
    long i = (long)blockIdx.x * blockDim.x + threadIdx.x;
    if (i >= total) return;
    int row = (int)(i >> 7);
    int k = (int)(i & 127);
    float x = (row < nvalid) ? src[i] * __ldg(&inv[row]) : 0.f;
    __nv_bfloat16 h = __float2bfloat16(x);
    float r1 = x - __bfloat162float(h);
    __nv_bfloat16 m = __float2bfloat16(r1);
    float r2 = r1 - __bfloat162float(m);
    size_t rb = (size_t)row * KEXT;
    dst[rb + k] = h;
    dst[rb + 128 + k] = m;
    dst[rb + 256 + k] = __float2bfloat16(r2);
}

// ---------------- main: bf16x6 mma.sync GEMM + fused epilogue ----------------
__device__ __forceinline__ void issue_step(int s, int mbase, int nbase,
                                           uint32_t sA, uint32_t sB, int tid) {
    const int blk = s >> 1, half = s & 1;
    const int am = (blk >= 3) + (blk >= 5);                   // A limb map {0,0,0,1,1,2}
    const int bm = (blk < 3) ? blk : ((blk < 5) ? (blk - 3) : 0); // B map {0,1,2,0,1,0}
    const int a16 = am * 16 + half * 8;                       // 16B-chunk offsets into KEXT
    const int b16 = bm * 16 + half * 8;
    #pragma unroll
    for (int j = 0; j < 2; j++) {
        int i = tid + j * NT;
        int row = i >> 3, c = i & 7;
        const void* g = (const void*)(g_aext + (size_t)(mbase + row) * KEXT + (size_t)(a16 + c) * 8);
        uint32_t sa = sA + row * 128 + (((uint32_t)(c ^ (row & 7))) << 4);
        CP_ASYNC16(sa, g);
    }
    #pragma unroll
    for (int j = 0; j < 4; j++) {
        int i = tid + j * NT;
        int row = i >> 3, c = i & 7;
        const void* g = (const void*)(g_bext + (size_t)(nbase + row) * KEXT + (size_t)(b16 + c) * 8);
        uint32_t sa = sB + row * 128 + (((uint32_t)(c ^ (row & 7))) << 4);
        CP_ASYNC16(sa, g);
    }
    CP_COMMIT();
}

__global__ void __launch_bounds__(NT, 1)
main_kernel(int B, int P) {
    extern __shared__ char smem[];
    const uint32_t sbase = smem_u32(smem);
    const int tid = threadIdx.x;
    const int lane = tid & 31;
    const int wid = tid >> 5;
    const int wm = wid & 3;            // warp M index (4)
    const int wn = wid >> 2;           // warp N index (4)
    const int mbase = blockIdx.y * BM;
    const int nbase = blockIdx.x * BN;

    float acc[2][8][4];
    #pragma unroll
    for (int mt = 0; mt < 2; mt++)
        #pragma unroll
        for (int nt = 0; nt < 8; nt++)
            #pragma unroll
            for (int c = 0; c < 4; c++) acc[mt][nt][c] = 0.f;

    // ldmatrix lane addressing (XOR swizzle on 128B rows)
    const int rowA = wm * 32 + (lane & 15);
    const int swA = rowA & 7;
    const int rowB = wn * 64 + (lane & 7) + ((lane >> 4) << 3);
    const int cB = (lane >> 3) & 1;
    const int swB = lane & 7;

    issue_step(0, mbase, nbase, sbase,          sbase + 16384,          tid);
    issue_step(1, mbase, nbase, sbase + BUFSZ,  sbase + BUFSZ + 16384,  tid);

    for (int s = 0; s < KSTEPS; s++) {
        if (s + 1 < KSTEPS) asm volatile("cp.async.wait_group 1;" ::: "memory");
        else                asm volatile("cp.async.wait_group 0;" ::: "memory");
        __syncthreads();
        const uint32_t bufA = sbase + (uint32_t)(s & 1) * BUFSZ;
        const uint32_t bufB = bufA + 16384;

        #pragma unroll
        for (int k16 = 0; k16 < 4; k16++) {
            uint32_t a[2][4];
            #pragma unroll
            for (int mt = 0; mt < 2; mt++) {
                uint32_t ad = bufA + (uint32_t)(rowA + mt * 16) * 128
                            + ((uint32_t)(((k16 * 2) + (lane >> 4)) ^ swA) << 4);
                LDSM_X4(a[mt][0], a[mt][1], a[mt][2], a[mt][3], ad);
            }
            uint32_t b[8][2];
            #pragma unroll
            for (int ng = 0; ng < 4; ng++) {
                uint32_t bd = bufB + (uint32_t)(rowB + ng * 16) * 128
                            + ((uint32_t)(((k16 * 2) + cB) ^ swB) << 4);
                LDSM_X4(b[ng * 2][0], b[ng * 2][1], b[ng * 2 + 1][0], b[ng * 2 + 1][1], bd);
            }
            #pragma unroll
            for (int mt = 0; mt < 2; mt++)
                #pragma unroll
                for (int nt = 0; nt < 8; nt++)
                    MMA_BF16(acc[mt][nt], a[mt], b[nt]);
        }
        __syncthreads();
        if (s + 2 < KSTEPS)
            issue_step(s + 2, mbase, nbase,
                       sbase + (uint32_t)(s & 1) * BUFSZ,
                       sbase + (uint32_t)(s & 1) * BUFSZ + 16384, tid);
    }

    // -------- fused epilogue on register fragments --------
    float* ez = (float*)smem;                 // [4][128]
    float* ev = ez + 4 * 128;                 // [4][128][3]
    int*   ei = (int*)(ev + 4 * 128 * 3);     // [4][128][3]

    #pragma unroll
    for (int mt = 0; mt < 2; mt++) {
        #pragma unroll
        for (int half = 0; half < 2; half++) {
            const int rloc = wm * 32 + mt * 16 + (lane >> 2) + half * 8;
            float z = 0.f;
            float v0 = -FLT_MAX, v1 = -FLT_MAX, v2 = -FLT_MAX;
            int   i0 = 0x7fffffff, i1 = 0x7fffffff, i2 = 0x7fffffff;
            #pragma unroll
            for (int nt = 0; nt < 8; nt++) {
                const int col = nbase + wn * 64 + nt * 8 + 2 * (lane & 3);
                const float c0 = acc[mt][nt][half * 2];
                const float c1 = acc[mt][nt][half * 2 + 1];
                if (col < P)     { z += expq5(c0); ins_stream(c0, col,     v0, i0, v1, i1, v2, i2); }
                if (col + 1 < P) { z += expq5(c1); ins_stream(c1, col + 1, v0, i0, v1, i1, v2, i2); }
            }
            // merge across the quad (lanes sharing this row)
            #pragma unroll
            for (int m = 1; m <= 2; m <<= 1) {
                z += __shfl_xor_sync(0xffffffffu, z, m);
                float ov0 = __shfl_xor_sync(0xffffffffu, v0, m);
                int   oi0 = __shfl_xor_sync(0xffffffffu, i0, m);
                float ov1 = __shfl_xor_sync(0xffffffffu, v1, m);
                int   oi1 = __shfl_xor_sync(0xffffffffu, i1, m);
                float ov2 = __shfl_xor_sync(0xffffffffu, v2, m);
                int   oi2 = __shfl_xor_sync(0xffffffffu, i2, m);
                ins_tie(ov0, oi0, v0, i0, v1, i1, v2, i2);
                ins_tie(ov1, oi1, v0, i0, v1, i1, v2, i2);
                ins_tie(ov2, oi2, v0, i0, v1, i1, v2, i2);
            }
            if ((lane & 3) == 0) {
                const int slot = wn * 128 + rloc;
                ez[slot] = z;
                ev[slot * 3 + 0] = v0; ei[slot * 3 + 0] = i0;
                ev[slot * 3 + 1] = v1; ei[slot * 3 + 1] = i1;
                ev[slot * 3 + 2] = v2; ei[slot * 3 + 2] = i2;
            }
        }
    }
    __syncthreads();

    if (tid < 128) {
        const int r = tid;
        float Z = 0.f;
        float v0 = -FLT_MAX, v1 = -FLT_MAX, v2 = -FLT_MAX;
        int   i0 = 0x7fffffff, i1 = 0x7fffffff, i2 = 0x7fffffff;
        #pragma unroll
        for (int w = 0; w < 4; w++) {
            const int slot = w * 128 + r;
            Z += ez[slot];
            ins_tie(ev[slot * 3 + 0], ei[slot * 3 + 0], v0, i0, v1, i1, v2, i2);
            ins_tie(ev[slot * 3 + 1], ei[slot * 3 + 1], v0, i0, v1, i1, v2, i2);
            ins_tie(ev[slot * 3 + 2], ei[slot * 3 + 2], v0, i0, v1, i1, v2, i2);
        }
        const int grow = mbase + r;
        if (grow < B) {
            size_t base = (size_t)grow * CHMAX + blockIdx.x;
            g_part_sum[base] = Z;
            g_part_val[base * 3 + 0] = v0; g_part_idx[base * 3 + 0] = i0;
            g_part_val[base * 3 + 1] = v1; g_part_idx[base * 3 + 1] = i1;
            g_part_val[base * 3 + 2] = v2; g_part_idx[base * 3 + 2] = i2;
        }
    }
}

// ---------------- kernel 4: per-row merge + softmaxes + gather ----------------
__global__ void reduce_kernel(const float* __restrict__ pool, float* __restrict__ out,
                              int B, int P, int nchunk) {
    int warp = (blockIdx.x * blockDim.x + threadIdx.x) >> 5;
    int lane = threadIdx.x & 31;
    if (warp >= B) return;
    const int row = warp;

    float Z = 0.f;
    float v0 = -FLT_MAX, v1 = -FLT_MAX, v2 = -FLT_MAX;
    int   i0 = 0x7fffffff, i1 = 0x7fffffff, i2 = 0x7fffffff;
    for (int c = lane; c < nchunk; c += 32) {
        size_t base = (size_t)row * CHMAX + c;
        Z += g_part_sum[base];
        ins_tie(g_part_val[base * 3 + 0], g_part_idx[base * 3 + 0], v0, i0, v1, i1, v2, i2);
        ins_tie(g_part_val[base * 3 + 1], g_part_idx[base * 3 + 1], v0, i0, v1, i1, v2, i2);
        ins_tie(g_part_val[base * 3 + 2], g_part_idx[base * 3 + 2], v0, i0, v1, i1, v2, i2);
    }
    #pragma unroll
    for (int m = 16; m; m >>= 1) {
        Z += __shfl_xor_sync(0xffffffffu, Z, m);
        float ov0 = __shfl_xor_sync(0xffffffffu, v0, m);
        int   oi0 = __shfl_xor_sync(0xffffffffu, i0, m);
        float ov1 = __shfl_xor_sync(0xffffffffu, v1, m);
        int   oi1 = __shfl_xor_sync(0xffffffffu, i1, m);
        float ov2 = __shfl_xor_sync(0xffffffffu, v2, m);
        int   oi2 = __shfl_xor_sync(0xffffffffu, i2, m);
        ins_tie(ov0, oi0, v0, i0, v1, i1, v2, i2);
        ins_tie(ov1, oi1, v0, i0, v1, i1, v2, i2);
        ins_tie(ov2, oi2, v0, i0, v1, i1, v2, i2);
    }

    float iz = 1.0f / Z;
    float p0 = expq7(v0) * iz, p1 = expq7(v1) * iz, p2 = expq7(v2) * iz;
    float mx = fmaxf(p0, fmaxf(p1, p2));
    float e0 = expf(p0 - mx), e1 = expf(p1 - mx), e2 = expf(p2 - mx);
    float si = 1.0f / (e0 + e1 + e2);
    float w0 = e0 * si, w1 = e1 * si, w2 = e2 * si;

    const size_t cos_off = (size_t)B * D;
    if (lane == 0) {
        out[cos_off + (size_t)row * 3 + 0] = w0;
        out[cos_off + (size_t)row * 3 + 1] = w1;
        out[cos_off + (size_t)row * 3 + 2] = w2;
    }

    float4 q0 = ((const float4*)(pool + (size_t)i0 * D))[lane];
    float4 q1 = ((const float4*)(pool + (size_t)i1 * D))[lane];
    float4 q2 = ((const float4*)(pool + (size_t)i2 * D))[lane];
    float4 nb;
    nb.x = fmaf(w0, q0.x, fmaf(w1, q1.x, w2 * q2.x));
    nb.y = fmaf(w0, q0.y, fmaf(w1, q1.y, w2 * q2.y));
    nb.z = fmaf(w0, q0.z, fmaf(w1, q1.z, w2 * q2.z));
    nb.w = fmaf(w0, q0.w, fmaf(w1, q1.w, w2 * q2.w));
    ((float4*)(out + (size_t)row * D))[lane] = nb;

    const size_t sb = cos_off + (size_t)B * 3;
    ((float4*)(out + sb + ((size_t)row * 3 + 0) * D))[lane] = q0;
    ((float4*)(out + sb + ((size_t)row * 3 + 1) * D))[lane] = q1;
    ((float4*)(out + sb + ((size_t)row * 3 + 2) * D))[lane] = q2;
}

// ---------------- launch ----------------
extern "C" void kernel_launch(void* const* d_in, const int* in_sizes, int n_in,
                              void* d_out, int out_size) {
    const float* sess = (const float*)d_in[0];
    const float* pool = (const float*)d_in[1];
    float* out = (float*)d_out;
    const int B = in_sizes[0] / D;
    const int P = in_sizes[1] / D;

    float *inv_pn, *inv_sn;
    __nv_bfloat16 *aext, *bext;
    cudaGetSymbolAddress((void**)&inv_pn, g_inv_pn);
    cudaGetSymbolAddress((void**)&inv_sn, g_inv_sn);
    cudaGetSymbolAddress((void**)&aext, g_aext);
    cudaGetSymbolAddress((void**)&bext, g_bext);

    norm_kernel<<<(P + 7) / 8, 256>>>(pool, P, inv_pn);
    norm_kernel<<<(B + 7) / 8, 256>>>(sess, B, inv_sn);

    const int ntiles = (P + BN - 1) / BN;       // 391
    const int mtiles = (B + BM - 1) / BM;       // 16
    const long ptotal = (long)ntiles * BN * D;
    const long stotal = (long)mtiles * BM * D;
    split_kernel<<<(unsigned)((ptotal + 255) / 256), 256>>>(pool, inv_pn, P, ptotal, bext);
    split_kernel<<<(unsigned)((stotal + 255) / 256), 256>>>(sess, inv_sn, B, stotal, aext);

    const int smem = 2 * BUFSZ;                 // 96 KB
    cudaFuncSetAttribute(main_kernel, cudaFuncAttributeMaxDynamicSharedMemorySize, smem);
    main_kernel<<<dim3(ntiles, mtiles), NT, smem>>>(B, P);

    reduce_kernel<<<(B * 32 + 255) / 256, 256>>>(pool, out, B, P, ntiles);
}

// round 6
// speedup vs baseline: 2.8945x; 2.2239x over previous
#include <cuda_runtime.h>
#include <cuda_fp16.h>
#include <math.h>
#include <float.h>
#include <stdint.h>

#define D 128
#define BM 128
#define SUBN 128
#define NSUB 8
#define CHCOLS 1024        // columns per CTA chunk
#define NCHMAX 128
#define MAXB 4096
#define PROWS 131072

// ---------------- device scratch ----------------
__device__ __half g_ah[(size_t)MAXB * D];
__device__ __half g_bh[(size_t)PROWS * D];
__device__ float g_inv_pn[PROWS];
__device__ float g_inv_sn[MAXB];
__device__ float g_pz[(size_t)MAXB * NCHMAX];
__device__ float g_pv[(size_t)MAXB * NCHMAX * 6];
__device__ int   g_pi[(size_t)MAXB * NCHMAX * 6];

// ---------------- PTX helpers ----------------
__device__ __forceinline__ uint32_t smem_u32(const void* p) {
    uint32_t a;
    asm("{ .reg .u64 t; cvta.to.shared.u64 t, %1; cvt.u32.u64 %0, t; }" : "=r"(a) : "l"(p));
    return a;
}
#define LDSM_X4(r0, r1, r2, r3, addr) \
    asm volatile("ldmatrix.sync.aligned.m8n8.x4.shared.b16 {%0,%1,%2,%3}, [%4];" \
                 : "=r"(r0), "=r"(r1), "=r"(r2), "=r"(r3) : "r"(addr))
#define MMA4(d, a0, a1, a2, a3, b0, b1) \
    asm volatile("mma.sync.aligned.m16n8k16.row.col.f32.f16.f16.f32 " \
                 "{%0,%1,%2,%3}, {%4,%5,%6,%7}, {%8,%9}, {%0,%1,%2,%3};" \
                 : "+f"((d)[0]), "+f"((d)[1]), "+f"((d)[2]), "+f"((d)[3]) \
                 : "r"(a0), "r"(a1), "r"(a2), "r"(a3), "r"(b0), "r"(b1))
#define CP_ASYNC16(sa, ga) \
    asm volatile("cp.async.cg.shared.global [%0], [%1], 16;" :: "r"(sa), "l"(ga))
#define CP_COMMIT() asm volatile("cp.async.commit_group;" ::: "memory")
template <int N>
__device__ __forceinline__ void cp_wait() {
    asm volatile("cp.async.wait_group %0;" :: "n"(N) : "memory");
}

// ---------------- math helpers ----------------
__device__ __forceinline__ float expq4(float x) {   // Z-sum exp: deg-4 Taylor (ample: Z needs ~1e-4)
    float r = 4.1666667e-2f;
    r = fmaf(r, x, 1.6666667e-1f);
    r = fmaf(r, x, 0.5f);
    r = fmaf(r, x, 1.0f);
    r = fmaf(r, x, 1.0f);
    return r;
}
__device__ __forceinline__ float expq7(float x) {   // high-acc exp for the 3 winners
    float r = 1.9841270e-4f;
    r = fmaf(r, x, 1.3888889e-3f);
    r = fmaf(r, x, 8.3333333e-3f);
    r = fmaf(r, x, 4.1666667e-2f);
    r = fmaf(r, x, 1.6666667e-1f);
    r = fmaf(r, x, 0.5f);
    r = fmaf(r, x, 1.0f);
    r = fmaf(r, x, 1.0f);
    return r;
}
__device__ __forceinline__ bool bet(float a, int ai, float b, int bi) {
    return (a > b) || (a == b && ai < bi);
}
// streaming top-6 insert (stream index increasing: strict > preserves tie order)
__device__ __forceinline__ void ins6s(float c, int ci, float* v, int* ix) {
    if (c > v[5]) {
        v[5] = c; ix[5] = ci;
        #pragma unroll
        for (int t = 5; t >= 1; t--) {
            if (v[t] > v[t - 1]) {
                float tv = v[t]; v[t] = v[t - 1]; v[t - 1] = tv;
                int   ti = ix[t]; ix[t] = ix[t - 1]; ix[t - 1] = ti;
            }
        }
    }
}
// merge top-6 insert with (value desc, index asc) tie-break
__device__ __forceinline__ void ins6t(float c, int ci, float* v, int* ix) {
    if (bet(c, ci, v[5], ix[5])) {
        v[5] = c; ix[5] = ci;
        #pragma unroll
        for (int t = 5; t >= 1; t--) {
            if (bet(v[t], ix[t], v[t - 1], ix[t - 1])) {
                float tv = v[t]; v[t] = v[t - 1]; v[t - 1] = tv;
                int   ti = ix[t]; ix[t] = ix[t - 1]; ix[t - 1] = ti;
            }
        }
    }
}
__device__ __forceinline__ void ins_tie3(float c, int ci,
    float& v0, int& i0, float& v1, int& i1, float& v2, int& i2) {
    if ((c > v2) || (c == v2 && ci < i2)) {
        if ((c > v1) || (c == v1 && ci < i1)) {
            if ((c > v0) || (c == v0 && ci < i0)) {
                v2 = v1; i2 = i1; v1 = v0; i1 = i0; v0 = c; i0 = ci;
            } else { v2 = v1; i2 = i1; v1 = c; i1 = ci; }
        } else     { v2 = c;  i2 = ci; }
    }
}

// ---------------- kernel 1: inverse norms ----------------
__global__ void norm_kernel(const float* __restrict__ x, int n, float* __restrict__ dst) {
    int row = blockIdx.x * (blockDim.x >> 5) + (threadIdx.x >> 5);
    if (row >= n) return;
    int lane = threadIdx.x & 31;
    float4 v = ((const float4*)(x + (size_t)row * D))[lane];
    float s = v.x * v.x + v.y * v.y + v.z * v.z + v.w * v.w;
    #pragma unroll
    for (int m = 16; m; m >>= 1) s += __shfl_xor_sync(0xffffffffu, s, m);
    if (lane == 0) dst[row] = 1.0f / sqrtf(s + (float)D * 1e-6f);
}

// ---------------- kernel 2: scale-by-inv-norm -> fp16 ----------------
__global__ void split_kernel(const float* __restrict__ src, const float* __restrict__ inv,
                             int nvalid, long total, __half* __restrict__ dst) {
    long i = (long)blockIdx.x * blockDim.x + threadIdx.x;
    if (i >= total) return;
    int row = (int)(i >> 7);
    float x = (row < nvalid) ? src[i] * __ldg(&inv[row]) : 0.f;
    dst[i] = __float2half_rn(x);
}

// ---------------- kernel 3: fp16 cos-GEMM + fused approx epilogue (Z, top-6) ----------------
__global__ void __launch_bounds__(256, 2)
main_kernel(int B, int P, int nchunk) {
    extern __shared__ char smem[];
    const uint32_t sA = smem_u32(smem);
    const uint32_t sB0 = sA + 32768u, sB1 = sB0 + 32768u;
    const int tid = threadIdx.x, lane = tid & 31, w = tid >> 5;
    const int mbase = blockIdx.y * BM;
    const int chbase = blockIdx.x * CHCOLS;

    // loader mapping: 256 threads, 16B chunks; rows of 256B, XOR-swizzled chunks
    const int lrow0 = tid >> 4, lc = tid & 15;

    // issue A tile + B subtile 0 (group 0), B subtile 1 (group 1)
    #pragma unroll
    for (int it = 0; it < 8; it++) {
        int row = lrow0 + it * 16;
        uint32_t sw = (uint32_t)((lc & 8) | ((lc ^ row) & 7));
        CP_ASYNC16(sA + row * 256 + sw * 16,
                   (const char*)g_ah + ((size_t)(mbase + row) * D + lc * 8) * 2);
    }
    #pragma unroll
    for (int it = 0; it < 8; it++) {
        int row = lrow0 + it * 16;
        uint32_t sw = (uint32_t)((lc & 8) | ((lc ^ row) & 7));
        CP_ASYNC16(sB0 + row * 256 + sw * 16,
                   (const char*)g_bh + ((size_t)(chbase + row) * D + lc * 8) * 2);
    }
    CP_COMMIT();
    #pragma unroll
    for (int it = 0; it < 8; it++) {
        int row = lrow0 + it * 16;
        uint32_t sw = (uint32_t)((lc & 8) | ((lc ^ row) & 7));
        CP_ASYNC16(sB1 + row * 256 + sw * 16,
                   (const char*)g_bh + ((size_t)(chbase + SUBN + row) * D + lc * 8) * 2);
    }
    CP_COMMIT();

    // fragment addressing
    const int rowA = w * 16 + (lane & 15);
    const int hiA = lane >> 4;
    const int rBb = (lane & 7) + ((lane >> 4) << 3);
    const int cB = (lane >> 3) & 1;

    float acc[16][4];
    float z[2] = {0.f, 0.f};
    float tv[2][6]; int ti[2][6];
    #pragma unroll
    for (int h = 0; h < 2; h++)
        #pragma unroll
        for (int t = 0; t < 6; t++) { tv[h][t] = -FLT_MAX; ti[h][t] = 0x7fffffff; }

    for (int s = 0; s < NSUB; s++) {
        if (s < NSUB - 1) cp_wait<1>(); else cp_wait<0>();
        __syncthreads();

        #pragma unroll
        for (int nt = 0; nt < 16; nt++)
            #pragma unroll
            for (int c = 0; c < 4; c++) acc[nt][c] = 0.f;

        const uint32_t bufB = (s & 1) ? sB1 : sB0;
        #pragma unroll
        for (int k16 = 0; k16 < 8; k16++) {
            int cA = k16 * 2 + hiA;
            uint32_t swA = (uint32_t)((cA & 8) | ((cA ^ rowA) & 7));
            uint32_t a0, a1, a2, a3;
            LDSM_X4(a0, a1, a2, a3, sA + rowA * 256 + swA * 16);
            #pragma unroll
            for (int ng = 0; ng < 8; ng++) {
                int rB = rBb + ng * 16;
                int cc = k16 * 2 + cB;
                uint32_t swB = (uint32_t)((cc & 8) | ((cc ^ rB) & 7));
                uint32_t b0, b1, b2, b3;
                LDSM_X4(b0, b1, b2, b3, bufB + rB * 256 + swB * 16);
                MMA4(acc[2 * ng],     a0, a1, a2, a3, b0, b1);
                MMA4(acc[2 * ng + 1], a0, a1, a2, a3, b2, b3);
            }
        }
        __syncthreads();

        // refill the just-consumed buffer with subtile s+2
        if (s + 2 < NSUB) {
            int nb = chbase + (s + 2) * SUBN;
            #pragma unroll
            for (int it = 0; it < 8; it++) {
                int row = lrow0 + it * 16;
                uint32_t sw = (uint32_t)((lc & 8) | ((lc ^ row) & 7));
                CP_ASYNC16(bufB + row * 256 + sw * 16,
                           (const char*)g_bh + ((size_t)(nb + row) * D + lc * 8) * 2);
            }
            CP_COMMIT();
        }

        // fused approx epilogue
        const int colbase = chbase + s * SUBN + 2 * (lane & 3);
        #pragma unroll
        for (int half = 0; half < 2; half++) {
            float zl = 0.f;
            #pragma unroll
            for (int nt = 0; nt < 16; nt++) {
                const int col = colbase + nt * 8;
                const float c0 = acc[nt][half * 2];
                const float c1 = acc[nt][half * 2 + 1];
                if (col < P)     { zl += expq4(c0); ins6s(c0, col,     tv[half], ti[half]); }
                if (col + 1 < P) { zl += expq4(c1); ins6s(c1, col + 1, tv[half], ti[half]); }
            }
            z[half] += zl;
        }
    }

    // quad merge (lanes sharing a row) + global partial write
    #pragma unroll
    for (int half = 0; half < 2; half++) {
        float zz = z[half];
        #pragma unroll
        for (int m = 1; m <= 2; m <<= 1) {
            zz += __shfl_xor_sync(0xffffffffu, zz, m);
            float ov[6]; int oi[6];
            #pragma unroll
            for (int t = 0; t < 6; t++) {
                ov[t] = __shfl_xor_sync(0xffffffffu, tv[half][t], m);
                oi[t] = __shfl_xor_sync(0xffffffffu, ti[half][t], m);
            }
            #pragma unroll
            for (int t = 0; t < 6; t++) ins6t(ov[t], oi[t], tv[half], ti[half]);
        }
        if ((lane & 3) == 0) {
            const int rg = mbase + w * 16 + (lane >> 2) + half * 8;
            if (rg < B) {
                size_t pb = (size_t)rg * nchunk + blockIdx.x;
                g_pz[pb] = zz;
                #pragma unroll
                for (int t = 0; t < 6; t++) {
                    g_pv[pb * 6 + t] = tv[half][t];
                    g_pi[pb * 6 + t] = ti[half][t];
                }
            }
        }
    }
}

// ---------------- kernel 4: merge chunks + exact fp32 refine + finalize ----------------
__global__ void finalize_kernel(const float* __restrict__ sess, const float* __restrict__ pool,
                                float* __restrict__ out, int B, int P, int nchunk) {
    const int row = blockIdx.x * 8 + (threadIdx.x >> 5);
    const int lane = threadIdx.x & 31;
    if (row >= B) return;

    float z = 0.f;
    float v[6]; int ix[6];
    #pragma unroll
    for (int t = 0; t < 6; t++) { v[t] = -FLT_MAX; ix[t] = 0x7fffffff; }

    for (int c = lane; c < nchunk; c += 32) {
        size_t pb = (size_t)row * nchunk + c;
        z += g_pz[pb];
        #pragma unroll
        for (int t = 0; t < 6; t++) ins6t(g_pv[pb * 6 + t], g_pi[pb * 6 + t], v, ix);
    }
    #pragma unroll
    for (int m = 16; m; m >>= 1) {
        z += __shfl_xor_sync(0xffffffffu, z, m);
        float ov[6]; int oi[6];
        #pragma unroll
        for (int t = 0; t < 6; t++) {
            ov[t] = __shfl_xor_sync(0xffffffffu, v[t], m);
            oi[t] = __shfl_xor_sync(0xffffffffu, ix[t], m);
        }
        #pragma unroll
        for (int t = 0; t < 6; t++) ins6t(ov[t], oi[t], v, ix);
    }

    // exact fp32 refinement of the 6 candidates
    const float4 sv = ((const float4*)(sess + (size_t)row * D))[lane];
    const float invs = g_inv_sn[row];
    float rc[6];
    #pragma unroll
    for (int j = 0; j < 6; j++) {
        const float4 q = ((const float4*)(pool + (size_t)ix[j] * D))[lane];
        float d = fmaf(sv.x, q.x, fmaf(sv.y, q.y, fmaf(sv.z, q.z, sv.w * q.w)));
        #pragma unroll
        for (int m = 16; m; m >>= 1) d += __shfl_xor_sync(0xffffffffu, d, m);
        rc[j] = d * invs * g_inv_pn[ix[j]];
    }
    float v0 = -FLT_MAX, v1 = -FLT_MAX, v2 = -FLT_MAX;
    int   i0 = 0x7fffffff, i1 = 0x7fffffff, i2 = 0x7fffffff;
    #pragma unroll
    for (int j = 0; j < 6; j++) ins_tie3(rc[j], ix[j], v0, i0, v1, i1, v2, i2);

    const float iz = 1.0f / z;
    const float p0 = expq7(v0) * iz, p1 = expq7(v1) * iz, p2 = expq7(v2) * iz;
    const float mx = fmaxf(p0, fmaxf(p1, p2));
    const float e0 = expf(p0 - mx), e1 = expf(p1 - mx), e2 = expf(p2 - mx);
    const float si = 1.0f / (e0 + e1 + e2);
    const float w0 = e0 * si, w1 = e1 * si, w2 = e2 * si;

    const size_t cos_off = (size_t)B * D;
    if (lane == 0) {
        out[cos_off + (size_t)row * 3 + 0] = w0;
        out[cos_off + (size_t)row * 3 + 1] = w1;
        out[cos_off + (size_t)row * 3 + 2] = w2;
    }
    const float4 q0 = ((const float4*)(pool + (size_t)i0 * D))[lane];
    const float4 q1 = ((const float4*)(pool + (size_t)i1 * D))[lane];
    const float4 q2 = ((const float4*)(pool + (size_t)i2 * D))[lane];
    float4 nb;
    nb.x = fmaf(w0, q0.x, fmaf(w1, q1.x, w2 * q2.x));
    nb.y = fmaf(w0, q0.y, fmaf(w1, q1.y, w2 * q2.y));
    nb.z = fmaf(w0, q0.z, fmaf(w1, q1.z, w2 * q2.z));
    nb.w = fmaf(w0, q0.w, fmaf(w1, q1.w, w2 * q2.w));
    ((float4*)(out + (size_t)row * D))[lane] = nb;

    const size_t sb = cos_off + (size_t)B * 3;
    ((float4*)(out + sb + ((size_t)row * 3 + 0) * D))[lane] = q0;
    ((float4*)(out + sb + ((size_t)row * 3 + 1) * D))[lane] = q1;
    ((float4*)(out + sb + ((size_t)row * 3 + 2) * D))[lane] = q2;
}

// ---------------- launch ----------------
extern "C" void kernel_launch(void* const* d_in, const int* in_sizes, int n_in,
                              void* d_out, int out_size) {
    const float* sess = (const float*)d_in[0];
    const float* pool = (const float*)d_in[1];
    float* out = (float*)d_out;
    const int B = in_sizes[0] / D;
    const int P = in_sizes[1] / D;

    float *inv_pn, *inv_sn;
    __half *ah, *bh;
    cudaGetSymbolAddress((void**)&inv_pn, g_inv_pn);
    cudaGetSymbolAddress((void**)&inv_sn, g_inv_sn);
    cudaGetSymbolAddress((void**)&ah, g_ah);
    cudaGetSymbolAddress((void**)&bh, g_bh);

    norm_kernel<<<(P + 7) / 8, 256>>>(pool, P, inv_pn);
    norm_kernel<<<(B + 7) / 8, 256>>>(sess, B, inv_sn);

    const int nchunk = (P + CHCOLS - 1) / CHCOLS;     // 98 for P=100000
    const int mtiles = (B + BM - 1) / BM;             // 16
    const long ptotal = (long)nchunk * CHCOLS * D;
    const long stotal = (long)mtiles * BM * D;
    split_kernel<<<(unsigned)((ptotal + 255) / 256), 256>>>(pool, inv_pn, P, ptotal, bh);
    split_kernel<<<(unsigned)((stotal + 255) / 256), 256>>>(sess, inv_sn, B, stotal, ah);

    const int smem = 3 * 32768;                       // A + 2x B subtile buffers = 96 KB
    cudaFuncSetAttribute(main_kernel, cudaFuncAttributeMaxDynamicSharedMemorySize, smem);
    main_kernel<<<dim3(nchunk, mtiles), 256, smem>>>(B, P, nchunk);

    finalize_kernel<<<(B + 7) / 8, 256>>>(sess, pool, out, B, P, nchunk);
}